// round 1
// baseline (speedup 1.0000x reference)
#include <cuda_runtime.h>

#define R  2000
#define D  128
#define H  4
#define NMAX 500000

// ---------------- device scratch (no allocations allowed) ----------------
__device__ __align__(16) float g_qvec[D];      // seed query, flattened [128]
__device__ __align__(16) float g_A[D * H];     // A[d][h] = (Wk^T q_h)[d] / sqrt(D)
__device__ __align__(16) float g_c[4];         // bias term of scores per head
__device__ int   g_hist[R];
__device__ int   g_off[R + 1];
__device__ int   g_cursor[R];
__device__ int   g_perm[NMAX];
__device__ float g_deg[R];
__device__ __align__(16) float g_O[R * D];     // PMA output (pre-rFF)
__device__ __align__(16) float g_hfeat[R * D]; // O2 @ Wg^T
__device__ __align__(16) float g_accG[R * D];  // GCN scatter accumulator
__device__ __align__(16) float g_WoT[D * D];
__device__ __align__(16) float g_WgT[D * D];

// ---------------- init: zero accumulators / counters ----------------
__global__ void k_init() {
    int i = blockIdx.x * blockDim.x + threadIdx.x;
    if (i < R * D) g_accG[i] = 0.f;
    if (i < R) { g_deg[i] = 1.0f; g_hist[i] = 0; g_cursor[i] = 0; }
}

// ---------------- prep: q = Wq S + bq ; A = (Wk^T q)/sqrt(D) ; transposes ----------------
__global__ void k_prep(const float* __restrict__ S,  const float* __restrict__ Wq,
                       const float* __restrict__ bq, const float* __restrict__ Wk,
                       const float* __restrict__ bk, const float* __restrict__ Wo,
                       const float* __restrict__ Wg) {
    __shared__ float s_S[D];
    __shared__ float s_q[D];
    int t = threadIdx.x;  // 128 threads
    s_S[t] = S[t];
    __syncthreads();
    float acc = bq[t];
    for (int d = 0; d < D; d++) acc = fmaf(s_S[d], Wq[t * D + d], acc);
    s_q[t] = acc;
    g_qvec[t] = acc;
    __syncthreads();
    const float scale = 0.08838834764831845f;  // 1/sqrt(128)
    int d = t;
    float a0 = 0.f, a1 = 0.f, a2 = 0.f, a3 = 0.f;
    for (int e = 0; e < 32; e++) {
        a0 = fmaf(s_q[0 * 32 + e], Wk[(0 * 32 + e) * D + d], a0);
        a1 = fmaf(s_q[1 * 32 + e], Wk[(1 * 32 + e) * D + d], a1);
        a2 = fmaf(s_q[2 * 32 + e], Wk[(2 * 32 + e) * D + d], a2);
        a3 = fmaf(s_q[3 * 32 + e], Wk[(3 * 32 + e) * D + d], a3);
    }
    g_A[d * H + 0] = a0 * scale;
    g_A[d * H + 1] = a1 * scale;
    g_A[d * H + 2] = a2 * scale;
    g_A[d * H + 3] = a3 * scale;
    if (t < H) {
        float cc = 0.f;
        for (int e = 0; e < 32; e++) cc = fmaf(s_q[t * 32 + e], bk[t * 32 + e], cc);
        g_c[t] = cc * scale;
    }
    // transpose Wo, Wg for coalesced column access in k_ff
    for (int i = t; i < D * D; i += blockDim.x) {
        int j = i >> 7, dd = i & 127;
        g_WoT[dd * D + j] = Wo[i];
        g_WgT[dd * D + j] = Wg[i];
    }
}

// ---------------- zone histogram + in-degree (fused) ----------------
__global__ void k_hist_deg(const int* __restrict__ zone, const int* __restrict__ adj,
                           int N, int E) {
    int i = blockIdx.x * blockDim.x + threadIdx.x;
    if (i < N) {
        atomicAdd(&g_hist[zone[i]], 1);
    } else if (i < N + E) {
        int e = i - N;
        atomicAdd(&g_deg[adj[E + e]], 1.0f);
    }
}

// ---------------- exclusive scan over hist (single block) ----------------
__global__ void k_scan() {
    __shared__ int b0[2048], b1[2048];
    int t = threadIdx.x;  // 1024 threads
    b0[t]        = (t        < R) ? g_hist[t]        : 0;
    b0[t + 1024] = (t + 1024 < R) ? g_hist[t + 1024] : 0;
    __syncthreads();
    int* s = b0; int* d = b1;
    for (int off = 1; off < 2048; off <<= 1) {
        int i0 = t, i1 = t + 1024;
        d[i0] = s[i0] + ((i0 >= off) ? s[i0 - off] : 0);
        d[i1] = s[i1] + ((i1 >= off) ? s[i1 - off] : 0);
        __syncthreads();
        int* tmp = s; s = d; d = tmp;
    }
    if (t == 0) g_off[0] = 0;
    if (t < R)        g_off[t + 1]    = s[t];
    if (t + 1024 < R) g_off[t + 1025] = s[t + 1024];
}

// ---------------- scatter permutation (counting sort by zone) ----------------
__global__ void k_scatter(const int* __restrict__ zone, int N) {
    int i = blockIdx.x * blockDim.x + threadIdx.x;
    if (i < N) {
        int z = zone[i];
        int p = atomicAdd(&g_cursor[z], 1);
        g_perm[g_off[z] + p] = i;
    }
}

// ---------------- the big one: per-region softmax-weighted centroid + Wv matvec ----------------
// One block per region, 8 warps. Each warp owns one member row per iteration;
// lane holds 4 dims (float4). Single pass over x: accumulate sum(e*x) and sum(e),
// normalize at the end (scores are O(0.05) so exp needs no max subtraction).
__global__ void __launch_bounds__(256) k_region(const float* __restrict__ x,
                                                const float* __restrict__ Wv,
                                                const float* __restrict__ bv) {
    __shared__ __align__(16) float s_acc[8][4][128];
    __shared__ float s_den[8][4];
    __shared__ __align__(16) float s_pool[4 * 128];
    __shared__ float s_dtot[4];

    int r = blockIdx.x;
    int tid = threadIdx.x, lane = tid & 31, warp = tid >> 5;
    int d0 = lane * 4;

    float4 a0 = *(const float4*)&g_A[(d0 + 0) * H];
    float4 a1 = *(const float4*)&g_A[(d0 + 1) * H];
    float4 a2 = *(const float4*)&g_A[(d0 + 2) * H];
    float4 a3 = *(const float4*)&g_A[(d0 + 3) * H];
    float4 c4 = *(const float4*)g_c;

    float4 acc0 = make_float4(0.f, 0.f, 0.f, 0.f);
    float4 acc1 = acc0, acc2 = acc0, acc3 = acc0;
    float4 den  = acc0;

    int beg = g_off[r], end = g_off[r + 1];
    for (int i = beg + warp; i < end; i += 8) {
        int n = g_perm[i];
        float4 xv = __ldg((const float4*)x + (size_t)n * 32 + lane);
        // per-lane partial scores for the 4 heads
        float4 s;
        s.x = fmaf(xv.x, a0.x, fmaf(xv.y, a1.x, fmaf(xv.z, a2.x, xv.w * a3.x)));
        s.y = fmaf(xv.x, a0.y, fmaf(xv.y, a1.y, fmaf(xv.z, a2.y, xv.w * a3.y)));
        s.z = fmaf(xv.x, a0.z, fmaf(xv.y, a1.z, fmaf(xv.z, a2.z, xv.w * a3.z)));
        s.w = fmaf(xv.x, a0.w, fmaf(xv.y, a1.w, fmaf(xv.z, a2.w, xv.w * a3.w)));
        #pragma unroll
        for (int o = 16; o > 0; o >>= 1) {
            s.x += __shfl_xor_sync(0xffffffffu, s.x, o);
            s.y += __shfl_xor_sync(0xffffffffu, s.y, o);
            s.z += __shfl_xor_sync(0xffffffffu, s.z, o);
            s.w += __shfl_xor_sync(0xffffffffu, s.w, o);
        }
        float4 e;
        e.x = __expf(s.x + c4.x);
        e.y = __expf(s.y + c4.y);
        e.z = __expf(s.z + c4.z);
        e.w = __expf(s.w + c4.w);
        den.x += e.x; den.y += e.y; den.z += e.z; den.w += e.w;
        acc0.x = fmaf(e.x, xv.x, acc0.x); acc0.y = fmaf(e.x, xv.y, acc0.y);
        acc0.z = fmaf(e.x, xv.z, acc0.z); acc0.w = fmaf(e.x, xv.w, acc0.w);
        acc1.x = fmaf(e.y, xv.x, acc1.x); acc1.y = fmaf(e.y, xv.y, acc1.y);
        acc1.z = fmaf(e.y, xv.z, acc1.z); acc1.w = fmaf(e.y, xv.w, acc1.w);
        acc2.x = fmaf(e.z, xv.x, acc2.x); acc2.y = fmaf(e.z, xv.y, acc2.y);
        acc2.z = fmaf(e.z, xv.z, acc2.z); acc2.w = fmaf(e.z, xv.w, acc2.w);
        acc3.x = fmaf(e.w, xv.x, acc3.x); acc3.y = fmaf(e.w, xv.y, acc3.y);
        acc3.z = fmaf(e.w, xv.z, acc3.z); acc3.w = fmaf(e.w, xv.w, acc3.w);
    }
    *(float4*)&s_acc[warp][0][d0] = acc0;
    *(float4*)&s_acc[warp][1][d0] = acc1;
    *(float4*)&s_acc[warp][2][d0] = acc2;
    *(float4*)&s_acc[warp][3][d0] = acc3;
    if (lane == 0) {
        s_den[warp][0] = den.x; s_den[warp][1] = den.y;
        s_den[warp][2] = den.z; s_den[warp][3] = den.w;
    }
    __syncthreads();
    if (tid < 4) {
        float v = 0.f;
        #pragma unroll
        for (int w = 0; w < 8; w++) v += s_den[w][tid];
        s_dtot[tid] = fmaxf(v, 1e-30f);
    }
    __syncthreads();
    for (int i = tid; i < 512; i += 256) {
        int h = i >> 7, d = i & 127;
        float v = 0.f;
        #pragma unroll
        for (int w = 0; w < 8; w++) v += s_acc[w][h][d];
        s_pool[i] = v / s_dtot[h];
    }
    __syncthreads();
    // pooled[j] = Wv[j,:] . xbar[h(j),:] + bv[j] ; O = q + pooled
    if (tid < 128) {
        int j = tid, h = j >> 5;
        const float4* wr = (const float4*)(Wv + (size_t)j * D);
        const float4* xb = (const float4*)(s_pool + h * D);
        float acc = 0.f;
        #pragma unroll 8
        for (int tt = 0; tt < 32; tt++) {
            float4 w = wr[tt]; float4 b = xb[tt];
            acc = fmaf(w.x, b.x, fmaf(w.y, b.y, fmaf(w.z, b.z, fmaf(w.w, b.w, acc))));
        }
        g_O[r * D + j] = g_qvec[j] + acc + bv[j];
    }
}

// ---------------- fused rFF (O += relu(O@Wo^T + bo)) and h = O2 @ Wg^T ----------------
// 16 regions per block, 256 threads: j = tid&127 output channel, tid>>7 picks 8-row half.
__global__ void __launch_bounds__(256) k_ff(const float* __restrict__ bo) {
    const int RPB = 16, PAD = 20;
    __shared__ __align__(16) float OsmT[128 * PAD];
    __shared__ __align__(16) float O2T[128 * PAD];
    int r0 = blockIdx.x * RPB;
    int tid = threadIdx.x;
    int j = tid & 127;
    int rr0 = (tid >> 7) * 8;

    for (int i = tid; i < RPB * D; i += 256) {
        int rr = i >> 7, d = i & 127;
        OsmT[d * PAD + rr] = g_O[(r0 + rr) * D + d];
    }
    __syncthreads();

    float acc[8];
    #pragma unroll
    for (int k = 0; k < 8; k++) acc[k] = 0.f;
    for (int d = 0; d < D; d++) {
        float w = g_WoT[d * D + j];
        const float4* o4 = (const float4*)&OsmT[d * PAD + rr0];
        float4 oa = o4[0], ob = o4[1];
        acc[0] = fmaf(w, oa.x, acc[0]); acc[1] = fmaf(w, oa.y, acc[1]);
        acc[2] = fmaf(w, oa.z, acc[2]); acc[3] = fmaf(w, oa.w, acc[3]);
        acc[4] = fmaf(w, ob.x, acc[4]); acc[5] = fmaf(w, ob.y, acc[5]);
        acc[6] = fmaf(w, ob.z, acc[6]); acc[7] = fmaf(w, ob.w, acc[7]);
    }
    float boj = bo[j];
    #pragma unroll
    for (int k = 0; k < 8; k++) {
        float t = acc[k] + boj;
        t = t > 0.f ? t : 0.f;
        O2T[j * PAD + rr0 + k] = OsmT[j * PAD + rr0 + k] + t;
    }
    __syncthreads();
    #pragma unroll
    for (int k = 0; k < 8; k++) acc[k] = 0.f;
    for (int d = 0; d < D; d++) {
        float w = g_WgT[d * D + j];
        const float4* o4 = (const float4*)&O2T[d * PAD + rr0];
        float4 oa = o4[0], ob = o4[1];
        acc[0] = fmaf(w, oa.x, acc[0]); acc[1] = fmaf(w, oa.y, acc[1]);
        acc[2] = fmaf(w, oa.z, acc[2]); acc[3] = fmaf(w, oa.w, acc[3]);
        acc[4] = fmaf(w, ob.x, acc[4]); acc[5] = fmaf(w, ob.y, acc[5]);
        acc[6] = fmaf(w, ob.z, acc[6]); acc[7] = fmaf(w, ob.w, acc[7]);
    }
    #pragma unroll
    for (int k = 0; k < 8; k++) g_hfeat[(r0 + rr0 + k) * D + j] = acc[k];
}

// ---------------- GCN edge scatter (incl. self loops) ----------------
__global__ void k_edge(const int* __restrict__ adj, int E) {
    int idx = blockIdx.x * blockDim.x + threadIdx.x;
    int total = (E + R) * 32;
    if (idx >= total) return;
    int e = idx >> 5, g = idx & 31, d0 = g * 4;
    int s, dt;
    if (e < E) { s = adj[e]; dt = adj[E + e]; }
    else       { s = dt = e - E; }
    float nrm = rsqrtf(g_deg[s]) * rsqrtf(g_deg[dt]);
    float4 hv = *(const float4*)&g_hfeat[s * D + d0];
    float* o = &g_accG[dt * D + d0];
    atomicAdd(o + 0, nrm * hv.x);
    atomicAdd(o + 1, nrm * hv.y);
    atomicAdd(o + 2, nrm * hv.z);
    atomicAdd(o + 3, nrm * hv.w);
}

// ---------------- bias + PReLU epilogue ----------------
__global__ void k_prelu(const float* __restrict__ bg, const float* __restrict__ pw,
                        float* __restrict__ out) {
    int i = blockIdx.x * blockDim.x + threadIdx.x;
    if (i < R * D) {
        int d = i & 127;
        float v = g_accG[i] + bg[d];
        out[i] = v > 0.f ? v : pw[d] * v;
    }
}

// ---------------- launcher ----------------
extern "C" void kernel_launch(void* const* d_in, const int* in_sizes, int n_in,
                              void* d_out, int out_size) {
    const float* x  = (const float*)d_in[0];
    const int* zone = (const int*)d_in[1];
    const int* adj  = (const int*)d_in[2];
    const float* S  = (const float*)d_in[3];
    const float* Wq = (const float*)d_in[4];
    const float* bq = (const float*)d_in[5];
    const float* Wk = (const float*)d_in[6];
    const float* bk = (const float*)d_in[7];
    const float* Wv = (const float*)d_in[8];
    const float* bv = (const float*)d_in[9];
    const float* Wo = (const float*)d_in[10];
    const float* bo = (const float*)d_in[11];
    const float* Wg = (const float*)d_in[12];
    const float* bg = (const float*)d_in[13];
    const float* pw = (const float*)d_in[14];
    float* out = (float*)d_out;
    int N = in_sizes[0] / D;
    int E = in_sizes[2] / 2;

    k_init<<<(R * D + 255) / 256, 256>>>();
    k_prep<<<1, 128>>>(S, Wq, bq, Wk, bk, Wo, Wg);
    k_hist_deg<<<(N + E + 255) / 256, 256>>>(zone, adj, N, E);
    k_scan<<<1, 1024>>>();
    k_scatter<<<(N + 255) / 256, 256>>>(zone, N);
    k_region<<<R, 256>>>(x, Wv, bv);
    k_ff<<<R / 16, 256>>>(bo);
    k_edge<<<((E + R) * 32 + 255) / 256, 256>>>(adj, E);
    k_prelu<<<(R * D + 255) / 256, 256>>>(bg, pw, out);
}

// round 3
// speedup vs baseline: 1.2794x; 1.2794x over previous
#include <cuda_runtime.h>

#define R  2000
#define D  128
#define H  4
#define NMAX 500000

// ---------------- device scratch (no allocations allowed) ----------------
__device__ __align__(16) float g_qvec[D];      // seed query, flattened [128]
__device__ __align__(16) float g_A[D * H];     // A[d][h] = (Wk^T q_h)[d] / sqrt(D)
__device__ __align__(16) float g_c[4];         // bias term of scores per head
__device__ int   g_hist[R];
__device__ int   g_off[R + 1];
__device__ int   g_cursor[R];
__device__ int   g_perm[NMAX];
__device__ float g_deg[R];
__device__ __align__(16) float g_O[R * D];     // PMA output (pre-rFF)
__device__ __align__(16) float g_hfeat[R * D]; // O2 @ Wg^T
__device__ __align__(16) float g_accG[R * D];  // GCN scatter accumulator
__device__ __align__(16) float g_WoT[D * D];
__device__ __align__(16) float g_WgT[D * D];

// ---------------- init: zero accumulators / counters ----------------
__global__ void k_init() {
    int i = blockIdx.x * blockDim.x + threadIdx.x;
    if (i < R * D) g_accG[i] = 0.f;
    if (i < R) { g_deg[i] = 1.0f; g_hist[i] = 0; g_cursor[i] = 0; }
}

// ---------------- prep: q = Wq S + bq ; A = (Wk^T q)/sqrt(D) ; transposes ----------------
__global__ void k_prep(const float* __restrict__ S,  const float* __restrict__ Wq,
                       const float* __restrict__ bq, const float* __restrict__ Wk,
                       const float* __restrict__ bk, const float* __restrict__ Wo,
                       const float* __restrict__ Wg) {
    __shared__ float s_S[D];
    __shared__ float s_q[D];
    int t = threadIdx.x;  // 128 threads
    s_S[t] = S[t];
    __syncthreads();
    float acc = bq[t];
    for (int d = 0; d < D; d++) acc = fmaf(s_S[d], Wq[t * D + d], acc);
    s_q[t] = acc;
    g_qvec[t] = acc;
    __syncthreads();
    const float scale = 0.08838834764831845f;  // 1/sqrt(128)
    int d = t;
    float a0 = 0.f, a1 = 0.f, a2 = 0.f, a3 = 0.f;
    for (int e = 0; e < 32; e++) {
        a0 = fmaf(s_q[0 * 32 + e], Wk[(0 * 32 + e) * D + d], a0);
        a1 = fmaf(s_q[1 * 32 + e], Wk[(1 * 32 + e) * D + d], a1);
        a2 = fmaf(s_q[2 * 32 + e], Wk[(2 * 32 + e) * D + d], a2);
        a3 = fmaf(s_q[3 * 32 + e], Wk[(3 * 32 + e) * D + d], a3);
    }
    g_A[d * H + 0] = a0 * scale;
    g_A[d * H + 1] = a1 * scale;
    g_A[d * H + 2] = a2 * scale;
    g_A[d * H + 3] = a3 * scale;
    if (t < H) {
        float cc = 0.f;
        for (int e = 0; e < 32; e++) cc = fmaf(s_q[t * 32 + e], bk[t * 32 + e], cc);
        g_c[t] = cc * scale;
    }
    // transpose Wo, Wg for coalesced column access in k_ff
    for (int i = t; i < D * D; i += blockDim.x) {
        int j = i >> 7, dd = i & 127;
        g_WoT[dd * D + j] = Wo[i];
        g_WgT[dd * D + j] = Wg[i];
    }
}

// ---------------- zone histogram + in-degree (fused) ----------------
__global__ void k_hist_deg(const int* __restrict__ zone, const int* __restrict__ adj,
                           int N, int E) {
    int i = blockIdx.x * blockDim.x + threadIdx.x;
    if (i < N) {
        atomicAdd(&g_hist[zone[i]], 1);
    } else if (i < N + E) {
        int e = i - N;
        atomicAdd(&g_deg[adj[E + e]], 1.0f);
    }
}

// ---------------- exclusive scan over hist (warp-scan, 1024 threads) ----------------
__global__ void k_scan() {
    int t = threadIdx.x, lane = t & 31, w = t >> 5;
    int i0 = 2 * t, i1 = 2 * t + 1;
    int v0 = (i0 < R) ? g_hist[i0] : 0;
    int v1 = (i1 < R) ? g_hist[i1] : 0;
    int s = v0 + v1;
    int incl = s;
    #pragma unroll
    for (int o = 1; o < 32; o <<= 1) {
        int n = __shfl_up_sync(0xffffffffu, incl, o);
        if (lane >= o) incl += n;
    }
    __shared__ int wsum[32];
    if (lane == 31) wsum[w] = incl;
    __syncthreads();
    if (w == 0) {
        int wi = wsum[lane];
        #pragma unroll
        for (int o = 1; o < 32; o <<= 1) {
            int n = __shfl_up_sync(0xffffffffu, wi, o);
            if (lane >= o) wi += n;
        }
        wsum[lane] = wi;
    }
    __syncthreads();
    int excl = incl - s + (w ? wsum[w - 1] : 0);
    if (i0 <= R) g_off[i0] = excl;
    if (i1 <= R) g_off[i1] = excl + v0;
}

// ---------------- scatter permutation (counting sort by zone) ----------------
__global__ void k_scatter(const int* __restrict__ zone, int N) {
    int i = blockIdx.x * blockDim.x + threadIdx.x;
    if (i < N) {
        int z = zone[i];
        int p = atomicAdd(&g_cursor[z], 1);
        g_perm[g_off[z] + p] = i;
    }
}

// ---------------- the big one: per-region softmax-weighted centroid + Wv matvec ----------------
// One block per region, 8 warps. Member indices staged in smem (no dependent
// perm->x chain); each warp processes 4 rows per iteration (MLP=4).
// Single pass over x: accumulate sum(e*x) and sum(e), normalize at the end
// (scores are O(0.05), so exp needs no max subtraction).
#define CHUNK 1024
__global__ void __launch_bounds__(256) k_region(const float* __restrict__ x,
                                                const float* __restrict__ Wv,
                                                const float* __restrict__ bv) {
    __shared__ __align__(16) float s_acc[8][4][128];
    __shared__ float s_den[8][4];
    __shared__ __align__(16) float s_pool[4 * 128];
    __shared__ float s_dtot[4];
    __shared__ int   s_idx[CHUNK];

    int r = blockIdx.x;
    int tid = threadIdx.x, lane = tid & 31, warp = tid >> 5;
    int d0 = lane * 4;

    float4 a0 = *(const float4*)&g_A[(d0 + 0) * H];
    float4 a1 = *(const float4*)&g_A[(d0 + 1) * H];
    float4 a2 = *(const float4*)&g_A[(d0 + 2) * H];
    float4 a3 = *(const float4*)&g_A[(d0 + 3) * H];
    float4 c4 = *(const float4*)g_c;

    float4 acc0 = make_float4(0.f, 0.f, 0.f, 0.f);
    float4 acc1 = acc0, acc2 = acc0, acc3 = acc0;
    float4 den  = acc0;

    int beg = g_off[r], end = g_off[r + 1];
    for (int cbeg = beg; cbeg < end; cbeg += CHUNK) {
        int cnt = end - cbeg;
        if (cnt > CHUNK) cnt = CHUNK;
        for (int i = tid; i < cnt; i += 256) s_idx[i] = g_perm[cbeg + i];
        __syncthreads();

        for (int base = warp * 4; base < cnt; base += 32) {
            int m = cnt - base;
            if (m >= 4) {
                int n0 = s_idx[base + 0], n1 = s_idx[base + 1];
                int n2 = s_idx[base + 2], n3 = s_idx[base + 3];
                float4 x0 = __ldcs((const float4*)x + (size_t)n0 * 32 + lane);
                float4 x1 = __ldcs((const float4*)x + (size_t)n1 * 32 + lane);
                float4 x2 = __ldcs((const float4*)x + (size_t)n2 * 32 + lane);
                float4 x3 = __ldcs((const float4*)x + (size_t)n3 * 32 + lane);
                float4 s0, s1, s2, s3;
                s0.x = fmaf(x0.x, a0.x, fmaf(x0.y, a1.x, fmaf(x0.z, a2.x, x0.w * a3.x)));
                s0.y = fmaf(x0.x, a0.y, fmaf(x0.y, a1.y, fmaf(x0.z, a2.y, x0.w * a3.y)));
                s0.z = fmaf(x0.x, a0.z, fmaf(x0.y, a1.z, fmaf(x0.z, a2.z, x0.w * a3.z)));
                s0.w = fmaf(x0.x, a0.w, fmaf(x0.y, a1.w, fmaf(x0.z, a2.w, x0.w * a3.w)));
                s1.x = fmaf(x1.x, a0.x, fmaf(x1.y, a1.x, fmaf(x1.z, a2.x, x1.w * a3.x)));
                s1.y = fmaf(x1.x, a0.y, fmaf(x1.y, a1.y, fmaf(x1.z, a2.y, x1.w * a3.y)));
                s1.z = fmaf(x1.x, a0.z, fmaf(x1.y, a1.z, fmaf(x1.z, a2.z, x1.w * a3.z)));
                s1.w = fmaf(x1.x, a0.w, fmaf(x1.y, a1.w, fmaf(x1.z, a2.w, x1.w * a3.w)));
                s2.x = fmaf(x2.x, a0.x, fmaf(x2.y, a1.x, fmaf(x2.z, a2.x, x2.w * a3.x)));
                s2.y = fmaf(x2.x, a0.y, fmaf(x2.y, a1.y, fmaf(x2.z, a2.y, x2.w * a3.y)));
                s2.z = fmaf(x2.x, a0.z, fmaf(x2.y, a1.z, fmaf(x2.z, a2.z, x2.w * a3.z)));
                s2.w = fmaf(x2.x, a0.w, fmaf(x2.y, a1.w, fmaf(x2.z, a2.w, x2.w * a3.w)));
                s3.x = fmaf(x3.x, a0.x, fmaf(x3.y, a1.x, fmaf(x3.z, a2.x, x3.w * a3.x)));
                s3.y = fmaf(x3.x, a0.y, fmaf(x3.y, a1.y, fmaf(x3.z, a2.y, x3.w * a3.y)));
                s3.z = fmaf(x3.x, a0.z, fmaf(x3.y, a1.z, fmaf(x3.z, a2.z, x3.w * a3.z)));
                s3.w = fmaf(x3.x, a0.w, fmaf(x3.y, a1.w, fmaf(x3.z, a2.w, x3.w * a3.w)));
                // 16 independent butterfly chains, interleaved for ILP
                #pragma unroll
                for (int o = 16; o > 0; o >>= 1) {
                    s0.x += __shfl_xor_sync(0xffffffffu, s0.x, o);
                    s1.x += __shfl_xor_sync(0xffffffffu, s1.x, o);
                    s2.x += __shfl_xor_sync(0xffffffffu, s2.x, o);
                    s3.x += __shfl_xor_sync(0xffffffffu, s3.x, o);
                    s0.y += __shfl_xor_sync(0xffffffffu, s0.y, o);
                    s1.y += __shfl_xor_sync(0xffffffffu, s1.y, o);
                    s2.y += __shfl_xor_sync(0xffffffffu, s2.y, o);
                    s3.y += __shfl_xor_sync(0xffffffffu, s3.y, o);
                    s0.z += __shfl_xor_sync(0xffffffffu, s0.z, o);
                    s1.z += __shfl_xor_sync(0xffffffffu, s1.z, o);
                    s2.z += __shfl_xor_sync(0xffffffffu, s2.z, o);
                    s3.z += __shfl_xor_sync(0xffffffffu, s3.z, o);
                    s0.w += __shfl_xor_sync(0xffffffffu, s0.w, o);
                    s1.w += __shfl_xor_sync(0xffffffffu, s1.w, o);
                    s2.w += __shfl_xor_sync(0xffffffffu, s2.w, o);
                    s3.w += __shfl_xor_sync(0xffffffffu, s3.w, o);
                }
                float4 e0, e1, e2, e3;
                e0.x = __expf(s0.x + c4.x); e0.y = __expf(s0.y + c4.y);
                e0.z = __expf(s0.z + c4.z); e0.w = __expf(s0.w + c4.w);
                e1.x = __expf(s1.x + c4.x); e1.y = __expf(s1.y + c4.y);
                e1.z = __expf(s1.z + c4.z); e1.w = __expf(s1.w + c4.w);
                e2.x = __expf(s2.x + c4.x); e2.y = __expf(s2.y + c4.y);
                e2.z = __expf(s2.z + c4.z); e2.w = __expf(s2.w + c4.w);
                e3.x = __expf(s3.x + c4.x); e3.y = __expf(s3.y + c4.y);
                e3.z = __expf(s3.z + c4.z); e3.w = __expf(s3.w + c4.w);
                den.x += e0.x + e1.x + e2.x + e3.x;
                den.y += e0.y + e1.y + e2.y + e3.y;
                den.z += e0.z + e1.z + e2.z + e3.z;
                den.w += e0.w + e1.w + e2.w + e3.w;
                acc0.x = fmaf(e0.x, x0.x, fmaf(e1.x, x1.x, fmaf(e2.x, x2.x, fmaf(e3.x, x3.x, acc0.x))));
                acc0.y = fmaf(e0.x, x0.y, fmaf(e1.x, x1.y, fmaf(e2.x, x2.y, fmaf(e3.x, x3.y, acc0.y))));
                acc0.z = fmaf(e0.x, x0.z, fmaf(e1.x, x1.z, fmaf(e2.x, x2.z, fmaf(e3.x, x3.z, acc0.z))));
                acc0.w = fmaf(e0.x, x0.w, fmaf(e1.x, x1.w, fmaf(e2.x, x2.w, fmaf(e3.x, x3.w, acc0.w))));
                acc1.x = fmaf(e0.y, x0.x, fmaf(e1.y, x1.x, fmaf(e2.y, x2.x, fmaf(e3.y, x3.x, acc1.x))));
                acc1.y = fmaf(e0.y, x0.y, fmaf(e1.y, x1.y, fmaf(e2.y, x2.y, fmaf(e3.y, x3.y, acc1.y))));
                acc1.z = fmaf(e0.y, x0.z, fmaf(e1.y, x1.z, fmaf(e2.y, x2.z, fmaf(e3.y, x3.z, acc1.z))));
                acc1.w = fmaf(e0.y, x0.w, fmaf(e1.y, x1.w, fmaf(e2.y, x2.w, fmaf(e3.y, x3.w, acc1.w))));
                acc2.x = fmaf(e0.z, x0.x, fmaf(e1.z, x1.x, fmaf(e2.z, x2.x, fmaf(e3.z, x3.x, acc2.x))));
                acc2.y = fmaf(e0.z, x0.y, fmaf(e1.z, x1.y, fmaf(e2.z, x2.y, fmaf(e3.z, x3.y, acc2.y))));
                acc2.z = fmaf(e0.z, x0.z, fmaf(e1.z, x1.z, fmaf(e2.z, x2.z, fmaf(e3.z, x3.z, acc2.z))));
                acc2.w = fmaf(e0.z, x0.w, fmaf(e1.z, x1.w, fmaf(e2.z, x2.w, fmaf(e3.z, x3.w, acc2.w))));
                acc3.x = fmaf(e0.w, x0.x, fmaf(e1.w, x1.x, fmaf(e2.w, x2.x, fmaf(e3.w, x3.x, acc3.x))));
                acc3.y = fmaf(e0.w, x0.y, fmaf(e1.w, x1.y, fmaf(e2.w, x2.y, fmaf(e3.w, x3.y, acc3.y))));
                acc3.z = fmaf(e0.w, x0.z, fmaf(e1.w, x1.z, fmaf(e2.w, x2.z, fmaf(e3.w, x3.z, acc3.z))));
                acc3.w = fmaf(e0.w, x0.w, fmaf(e1.w, x1.w, fmaf(e2.w, x2.w, fmaf(e3.w, x3.w, acc3.w))));
            } else {
                for (int j = 0; j < m; j++) {
                    int n = s_idx[base + j];
                    float4 xv = __ldcs((const float4*)x + (size_t)n * 32 + lane);
                    float4 s;
                    s.x = fmaf(xv.x, a0.x, fmaf(xv.y, a1.x, fmaf(xv.z, a2.x, xv.w * a3.x)));
                    s.y = fmaf(xv.x, a0.y, fmaf(xv.y, a1.y, fmaf(xv.z, a2.y, xv.w * a3.y)));
                    s.z = fmaf(xv.x, a0.z, fmaf(xv.y, a1.z, fmaf(xv.z, a2.z, xv.w * a3.z)));
                    s.w = fmaf(xv.x, a0.w, fmaf(xv.y, a1.w, fmaf(xv.z, a2.w, xv.w * a3.w)));
                    #pragma unroll
                    for (int o = 16; o > 0; o >>= 1) {
                        s.x += __shfl_xor_sync(0xffffffffu, s.x, o);
                        s.y += __shfl_xor_sync(0xffffffffu, s.y, o);
                        s.z += __shfl_xor_sync(0xffffffffu, s.z, o);
                        s.w += __shfl_xor_sync(0xffffffffu, s.w, o);
                    }
                    float4 e;
                    e.x = __expf(s.x + c4.x); e.y = __expf(s.y + c4.y);
                    e.z = __expf(s.z + c4.z); e.w = __expf(s.w + c4.w);
                    den.x += e.x; den.y += e.y; den.z += e.z; den.w += e.w;
                    acc0.x = fmaf(e.x, xv.x, acc0.x); acc0.y = fmaf(e.x, xv.y, acc0.y);
                    acc0.z = fmaf(e.x, xv.z, acc0.z); acc0.w = fmaf(e.x, xv.w, acc0.w);
                    acc1.x = fmaf(e.y, xv.x, acc1.x); acc1.y = fmaf(e.y, xv.y, acc1.y);
                    acc1.z = fmaf(e.y, xv.z, acc1.z); acc1.w = fmaf(e.y, xv.w, acc1.w);
                    acc2.x = fmaf(e.z, xv.x, acc2.x); acc2.y = fmaf(e.z, xv.y, acc2.y);
                    acc2.z = fmaf(e.z, xv.z, acc2.z); acc2.w = fmaf(e.z, xv.w, acc2.w);
                    acc3.x = fmaf(e.w, xv.x, acc3.x); acc3.y = fmaf(e.w, xv.y, acc3.y);
                    acc3.z = fmaf(e.w, xv.z, acc3.z); acc3.w = fmaf(e.w, xv.w, acc3.w);
                }
            }
        }
        __syncthreads();  // protect s_idx before next chunk overwrite
    }

    *(float4*)&s_acc[warp][0][d0] = acc0;
    *(float4*)&s_acc[warp][1][d0] = acc1;
    *(float4*)&s_acc[warp][2][d0] = acc2;
    *(float4*)&s_acc[warp][3][d0] = acc3;
    if (lane == 0) {
        s_den[warp][0] = den.x; s_den[warp][1] = den.y;
        s_den[warp][2] = den.z; s_den[warp][3] = den.w;
    }
    __syncthreads();
    if (tid < 4) {
        float v = 0.f;
        #pragma unroll
        for (int w = 0; w < 8; w++) v += s_den[w][tid];
        s_dtot[tid] = fmaxf(v, 1e-30f);
    }
    __syncthreads();
    for (int i = tid; i < 512; i += 256) {
        int h = i >> 7, d = i & 127;
        float v = 0.f;
        #pragma unroll
        for (int w = 0; w < 8; w++) v += s_acc[w][h][d];
        s_pool[i] = v / s_dtot[h];
    }
    __syncthreads();
    // pooled[j] = Wv[j,:] . xbar[h(j),:] + bv[j] ; O = q + pooled
    if (tid < 128) {
        int j = tid, h = j >> 5;
        const float4* wr = (const float4*)(Wv + (size_t)j * D);
        const float4* xb = (const float4*)(s_pool + h * D);
        float acc = 0.f;
        #pragma unroll 8
        for (int tt = 0; tt < 32; tt++) {
            float4 w = wr[tt]; float4 b = xb[tt];
            acc = fmaf(w.x, b.x, fmaf(w.y, b.y, fmaf(w.z, b.z, fmaf(w.w, b.w, acc))));
        }
        g_O[r * D + j] = g_qvec[j] + acc + bv[j];
    }
}

// ---------------- fused rFF (O += relu(O@Wo^T + bo)) and h = O2 @ Wg^T ----------------
__global__ void __launch_bounds__(256) k_ff(const float* __restrict__ bo) {
    const int RPB = 16, PAD = 20;
    __shared__ __align__(16) float OsmT[128 * PAD];
    __shared__ __align__(16) float O2T[128 * PAD];
    int r0 = blockIdx.x * RPB;
    int tid = threadIdx.x;
    int j = tid & 127;
    int rr0 = (tid >> 7) * 8;

    for (int i = tid; i < RPB * D; i += 256) {
        int rr = i >> 7, d = i & 127;
        OsmT[d * PAD + rr] = g_O[(r0 + rr) * D + d];
    }
    __syncthreads();

    float acc[8];
    #pragma unroll
    for (int k = 0; k < 8; k++) acc[k] = 0.f;
    for (int d = 0; d < D; d++) {
        float w = g_WoT[d * D + j];
        const float4* o4 = (const float4*)&OsmT[d * PAD + rr0];
        float4 oa = o4[0], ob = o4[1];
        acc[0] = fmaf(w, oa.x, acc[0]); acc[1] = fmaf(w, oa.y, acc[1]);
        acc[2] = fmaf(w, oa.z, acc[2]); acc[3] = fmaf(w, oa.w, acc[3]);
        acc[4] = fmaf(w, ob.x, acc[4]); acc[5] = fmaf(w, ob.y, acc[5]);
        acc[6] = fmaf(w, ob.z, acc[6]); acc[7] = fmaf(w, ob.w, acc[7]);
    }
    float boj = bo[j];
    #pragma unroll
    for (int k = 0; k < 8; k++) {
        float t = acc[k] + boj;
        t = t > 0.f ? t : 0.f;
        O2T[j * PAD + rr0 + k] = OsmT[j * PAD + rr0 + k] + t;
    }
    __syncthreads();
    #pragma unroll
    for (int k = 0; k < 8; k++) acc[k] = 0.f;
    for (int d = 0; d < D; d++) {
        float w = g_WgT[d * D + j];
        const float4* o4 = (const float4*)&O2T[d * PAD + rr0];
        float4 oa = o4[0], ob = o4[1];
        acc[0] = fmaf(w, oa.x, acc[0]); acc[1] = fmaf(w, oa.y, acc[1]);
        acc[2] = fmaf(w, oa.z, acc[2]); acc[3] = fmaf(w, oa.w, acc[3]);
        acc[4] = fmaf(w, ob.x, acc[4]); acc[5] = fmaf(w, ob.y, acc[5]);
        acc[6] = fmaf(w, ob.z, acc[6]); acc[7] = fmaf(w, ob.w, acc[7]);
    }
    #pragma unroll
    for (int k = 0; k < 8; k++) g_hfeat[(r0 + rr0 + k) * D + j] = acc[k];
}

// ---------------- GCN edge scatter (incl. self loops) ----------------
__global__ void k_edge(const int* __restrict__ adj, int E) {
    int idx = blockIdx.x * blockDim.x + threadIdx.x;
    int total = (E + R) * 32;
    if (idx >= total) return;
    int e = idx >> 5, g = idx & 31, d0 = g * 4;
    int s, dt;
    if (e < E) { s = adj[e]; dt = adj[E + e]; }
    else       { s = dt = e - E; }
    float nrm = rsqrtf(g_deg[s]) * rsqrtf(g_deg[dt]);
    float4 hv = *(const float4*)&g_hfeat[s * D + d0];
    float* o = &g_accG[dt * D + d0];
    atomicAdd(o + 0, nrm * hv.x);
    atomicAdd(o + 1, nrm * hv.y);
    atomicAdd(o + 2, nrm * hv.z);
    atomicAdd(o + 3, nrm * hv.w);
}

// ---------------- bias + PReLU epilogue ----------------
__global__ void k_prelu(const float* __restrict__ bg, const float* __restrict__ pw,
                        float* __restrict__ out) {
    int i = blockIdx.x * blockDim.x + threadIdx.x;
    if (i < R * D) {
        int d = i & 127;
        float v = g_accG[i] + bg[d];
        out[i] = v > 0.f ? v : pw[d] * v;
    }
}

// ---------------- launcher ----------------
extern "C" void kernel_launch(void* const* d_in, const int* in_sizes, int n_in,
                              void* d_out, int out_size) {
    const float* x  = (const float*)d_in[0];
    const int* zone = (const int*)d_in[1];
    const int* adj  = (const int*)d_in[2];
    const float* S  = (const float*)d_in[3];
    const float* Wq = (const float*)d_in[4];
    const float* bq = (const float*)d_in[5];
    const float* Wk = (const float*)d_in[6];
    const float* bk = (const float*)d_in[7];
    const float* Wv = (const float*)d_in[8];
    const float* bv = (const float*)d_in[9];
    const float* Wo = (const float*)d_in[10];
    const float* bo = (const float*)d_in[11];
    const float* Wg = (const float*)d_in[12];
    const float* bg = (const float*)d_in[13];
    const float* pw = (const float*)d_in[14];
    float* out = (float*)d_out;
    int N = in_sizes[0] / D;
    int E = in_sizes[2] / 2;

    k_init<<<(R * D + 255) / 256, 256>>>();
    k_prep<<<1, 128>>>(S, Wq, bq, Wk, bk, Wo, Wg);
    k_hist_deg<<<(N + E + 255) / 256, 256>>>(zone, adj, N, E);
    k_scan<<<1, 1024>>>();
    k_scatter<<<(N + 255) / 256, 256>>>(zone, N);
    k_region<<<R, 256>>>(x, Wv, bv);
    k_ff<<<R / 16, 256>>>(bo);
    k_edge<<<((E + R) * 32 + 255) / 256, 256>>>(adj, E);
    k_prelu<<<(R * D + 255) / 256, 256>>>(bg, pw, out);
}